// round 2
// baseline (speedup 1.0000x reference)
#include <cuda_runtime.h>

#define BATCH 64
#define CH 64
#define HH 112
#define WW 112
#define HWPIX (HH*WW)          // 12544
#define NP 128                 // pixels per tile
#define TILES_PER_BLK 7
#define BLKX 14                // 14*7 = 98 tiles = 12544/128
#define EPSV 1e-5f

// device scratch (no cudaMalloc allowed)
__device__ float g_context[BATCH*CH*CH];   // [b][c][d], 1 MB
__device__ float g_dynw[BATCH*CH*9];       // [b*c][9]

__device__ __forceinline__ unsigned long long pack2(float a, float b){
  unsigned long long r; asm("mov.b64 %0, {%1, %2};" : "=l"(r) : "f"(a), "f"(b)); return r;
}
__device__ __forceinline__ void fma2(unsigned long long &d, unsigned long long a, unsigned long long b){
  asm("fma.rn.f32x2 %0, %1, %2, %0;" : "+l"(d) : "l"(a), "l"(b));
}
__device__ __forceinline__ float2 unpack2(unsigned long long v){
  float lo, hi; asm("mov.b64 {%0, %1}, %2;" : "=f"(lo), "=f"(hi) : "l"(v));
  return make_float2(lo, hi);
}

// ---- smem layout (float offsets) for attn kernel ----
#define OFF_WS   0            // [128][64]  Wv rows 0-63, Wm rows 64-127 (persistent)
#define OFF_XS   8192         // [64][128]  x tile (per tile)
#define OFF_VT   8192         // [p][d]     value, pixel-major swizzled (reuses XS)
#define OFF_KT   16384        // [p][c]     softmaxed key, pixel-major swizzled
#define OFF_VB   24576        // 64
#define OFF_KSC  24640        // 64
#define OFF_KSH  24704        // 64
#define OFF_RED1 24768        // 128*9
#define OFF_RED2 25920        // 128*9
#define SMEM_FLOATS 27072
#define SMEM_BYTES (SMEM_FLOATS*4)

__global__ void __launch_bounds__(256) zero_ctx_kernel(){
  int i = blockIdx.x * blockDim.x + threadIdx.x;   // 65536 float4
  ((float4*)g_context)[i] = make_float4(0.f,0.f,0.f,0.f);
}

// Fused: V=Wv@X, K=softmax(BN(Wm@X)), context += K@V^T (per batch)
__global__ void __launch_bounds__(256, 2) attn_ctx_kernel(
    const float* __restrict__ x,
    const float* __restrict__ Wv, const float* __restrict__ bv,
    const float* __restrict__ Wm, const float* __restrict__ bm,
    const float* __restrict__ gma, const float* __restrict__ bta,
    const float* __restrict__ mu,  const float* __restrict__ var)
{
  extern __shared__ float sm[];
  const int tid = threadIdx.x;
  const int b   = blockIdx.y;
  const int tx  = tid & 15, ty = tid >> 4;
  const int r0  = ty * 8;        // stage-1 output rows (0-63 V, 64-127 K)
  const int c0  = tx * 8;        // stage-1 pixel cols
  const bool isK = (ty >= 8);
  const int  cb  = r0 - 64;      // K channel base (valid when isK)
  const int  g   = ty - 8;       // reduction slot (valid when isK)

  // persistent weight tile [Wv ; Wm] : 8192 floats
  for (int t = tid; t < 1024; t += 256) {
    ((float4*)(sm + OFF_WS))[t]        = ((const float4*)Wv)[t];
    ((float4*)(sm + OFF_WS + 4096))[t] = ((const float4*)Wm)[t];
  }
  if (tid < CH) {
    float sc = gma[tid] * rsqrtf(var[tid] + EPSV);
    sm[OFF_KSC + tid] = sc;
    sm[OFF_KSH + tid] = (bm[tid] - mu[tid]) * sc + bta[tid];
    sm[OFF_VB  + tid] = bv[tid];
  }
  __syncthreads();

  // stage-2 accumulators persist across tiles: 4x4 (c,d) per thread
  const int cr0 = (tid >> 4) * 4;   // context row (K channel)
  const int dr0 = (tid & 15) * 4;   // context col (V channel)
  unsigned long long ac2[4][2];
  #pragma unroll
  for (int i = 0; i < 4; i++){ ac2[i][0] = 0ULL; ac2[i][1] = 0ULL; }

  for (int t = 0; t < TILES_PER_BLK; t++) {
    const int tile = blockIdx.x * TILES_PER_BLK + t;
    const int n0 = tile * NP;

    // load x tile [64][128]  (sync A implied by loop structure: first iter after init sync,
    // later iters guarded by sync at loop bottom)
    for (int q = tid; q < 2048; q += 256) {
      int k = q >> 5, v = q & 31;
      ((float4*)(sm + OFF_XS + k*NP))[v] =
          ((const float4*)(x + (size_t)(b*CH + k)*HWPIX + n0))[v];
    }
    __syncthreads();

    // ---- stage 1: [128 rows] x [128 px], K-dim 64, f32x2 ----
    unsigned long long acc2[8][4];
    #pragma unroll
    for (int i = 0; i < 8; i++)
      #pragma unroll
      for (int jp = 0; jp < 4; jp++) acc2[i][jp] = 0ULL;

    #pragma unroll 4
    for (int k = 0; k < CH; k++) {
      ulonglong2 b01 = *(const ulonglong2*)&sm[OFF_XS + k*NP + c0];
      ulonglong2 b23 = *(const ulonglong2*)&sm[OFF_XS + k*NP + c0 + 4];
      unsigned long long bb0 = b01.x, bb1 = b01.y, bb2 = b23.x, bb3 = b23.y;
      #pragma unroll
      for (int i = 0; i < 8; i++) {
        float a = sm[OFF_WS + (r0 + i)*CH + k];
        unsigned long long a2 = pack2(a, a);
        fma2(acc2[i][0], a2, bb0);
        fma2(acc2[i][1], a2, bb1);
        fma2(acc2[i][2], a2, bb2);
        fma2(acc2[i][3], a2, bb3);
      }
    }

    float acc[8][8];
    #pragma unroll
    for (int i = 0; i < 8; i++)
      #pragma unroll
      for (int jp = 0; jp < 4; jp++) {
        float2 f = unpack2(acc2[i][jp]);
        acc[i][2*jp] = f.x; acc[i][2*jp + 1] = f.y;
      }

    // ---- slot 1: K: BN + partial max -> red1 ; V: bias ----
    if (isK) {
      #pragma unroll
      for (int i = 0; i < 8; i++) {
        float s1 = sm[OFF_KSC + cb + i], s2 = sm[OFF_KSH + cb + i];
        #pragma unroll
        for (int j = 0; j < 8; j++) acc[i][j] = acc[i][j]*s1 + s2;
      }
      #pragma unroll
      for (int j = 0; j < 8; j++) {
        float pm = acc[0][j];
        #pragma unroll
        for (int i = 1; i < 8; i++) pm = fmaxf(pm, acc[i][j]);
        sm[OFF_RED1 + (c0 + j)*9 + g] = pm;
      }
    } else {
      #pragma unroll
      for (int i = 0; i < 8; i++) {
        float bvi = sm[OFF_VB + r0 + i];
        #pragma unroll
        for (int j = 0; j < 8; j++) acc[i][j] += bvi;
      }
    }
    __syncthreads();

    // ---- slot 2: K: full max, exp, partial sum -> red2 ; V: write VT ----
    if (isK) {
      #pragma unroll
      for (int j = 0; j < 8; j++) {
        int p = c0 + j;
        float m = sm[OFF_RED1 + p*9];
        #pragma unroll
        for (int g2 = 1; g2 < 8; g2++) m = fmaxf(m, sm[OFF_RED1 + p*9 + g2]);
        float s = 0.f;
        #pragma unroll
        for (int i = 0; i < 8; i++) { acc[i][j] = __expf(acc[i][j] - m); s += acc[i][j]; }
        sm[OFF_RED2 + p*9 + g] = s;
      }
    } else {
      #pragma unroll
      for (int j = 0; j < 8; j++) {
        int p = c0 + j;
        int swz = ((p >> 3) & 7) << 2;
        float4 v0 = make_float4(acc[0][j], acc[1][j], acc[2][j], acc[3][j]);
        float4 v1 = make_float4(acc[4][j], acc[5][j], acc[6][j], acc[7][j]);
        *(float4*)&sm[OFF_VT + p*64 + ((r0    ) ^ swz)] = v0;
        *(float4*)&sm[OFF_VT + p*64 + ((r0 + 4) ^ swz)] = v1;
      }
    }
    __syncthreads();

    // ---- slot 3: K: total sum, normalize, write KT ----
    if (isK) {
      #pragma unroll
      for (int j = 0; j < 8; j++) {
        int p = c0 + j;
        float s = 0.f;
        #pragma unroll
        for (int g2 = 0; g2 < 8; g2++) s += sm[OFF_RED2 + p*9 + g2];
        float inv = 1.f / s;
        int swz = ((p >> 3) & 7) << 2;
        float4 k0 = make_float4(acc[0][j]*inv, acc[1][j]*inv, acc[2][j]*inv, acc[3][j]*inv);
        float4 k1 = make_float4(acc[4][j]*inv, acc[5][j]*inv, acc[6][j]*inv, acc[7][j]*inv);
        *(float4*)&sm[OFF_KT + p*64 + ((cb    ) ^ swz)] = k0;
        *(float4*)&sm[OFF_KT + p*64 + ((cb + 4) ^ swz)] = k1;
      }
    }
    __syncthreads();

    // ---- stage 2: context[c][d] += sum_p KT[p][c] * VT[p][d] ----
    #pragma unroll 2
    for (int p = 0; p < NP; p++) {
      int swz = ((p >> 3) & 7) << 2;
      float4 ka      = *(const float4*)&sm[OFF_KT + p*64 + (cr0 ^ swz)];
      ulonglong2 vv  = *(const ulonglong2*)&sm[OFF_VT + p*64 + (dr0 ^ swz)];
      unsigned long long a0 = pack2(ka.x, ka.x);
      unsigned long long a1 = pack2(ka.y, ka.y);
      unsigned long long a2 = pack2(ka.z, ka.z);
      unsigned long long a3 = pack2(ka.w, ka.w);
      fma2(ac2[0][0], a0, vv.x); fma2(ac2[0][1], a0, vv.y);
      fma2(ac2[1][0], a1, vv.x); fma2(ac2[1][1], a1, vv.y);
      fma2(ac2[2][0], a2, vv.x); fma2(ac2[2][1], a2, vv.y);
      fma2(ac2[3][0], a3, vv.x); fma2(ac2[3][1], a3, vv.y);
    }
    __syncthreads();   // guard: next tile overwrites XS/VT, KT
  }

  // one atomic flush per block
  float* ctx = g_context + (size_t)b*CH*CH;
  #pragma unroll
  for (int i = 0; i < 4; i++) {
    float2 f0 = unpack2(ac2[i][0]);
    float2 f1 = unpack2(ac2[i][1]);
    atomicAdd(&ctx[(cr0 + i)*CH + dr0 + 0], f0.x);
    atomicAdd(&ctx[(cr0 + i)*CH + dr0 + 1], f0.y);
    atomicAdd(&ctx[(cr0 + i)*CH + dr0 + 2], f1.x);
    atomicAdd(&ctx[(cr0 + i)*CH + dr0 + 3], f1.y);
  }
}

// dynw[b,i,j] = sum_m sigmoid(context[b,i,m]) * Wfc[i,j,m] + bfc[i,j]
__global__ void __launch_bounds__(128) dynw_kernel(
    const float* __restrict__ Wfc, const float* __restrict__ bfc)
{
  int warp = blockIdx.x * 4 + (threadIdx.x >> 5);   // 0..4095
  int lane = threadIdx.x & 31;
  int i = warp & 63;
  const float* ctx = g_context + (size_t)warp * 64;
  float a0 = 1.f / (1.f + __expf(-ctx[lane]));
  float a1 = 1.f / (1.f + __expf(-ctx[lane + 32]));
  #pragma unroll
  for (int j = 0; j < 9; j++) {
    float s = a0 * Wfc[(i*9 + j)*64 + lane] + a1 * Wfc[(i*9 + j)*64 + lane + 32];
    #pragma unroll
    for (int o = 16; o > 0; o >>= 1) s += __shfl_xor_sync(0xffffffffu, s, o);
    if (lane == 0) g_dynw[warp*9 + j] = s + bfc[i*9 + j];
  }
}

// depthwise 3x3, pad 1, per-(b,c) weights from g_dynw
#define TROWS 28
__global__ void __launch_bounds__(128) dwconv_kernel(
    const float* __restrict__ x, float* __restrict__ out)
{
  __shared__ float ts[(TROWS + 2) * 114];
  const int plane = blockIdx.x;                 // b*64 + c
  const int rb = blockIdx.y * TROWS;
  const float* xp = x + (size_t)plane * HWPIX;
  const int tid = threadIdx.x;

  for (int idx = tid; idx < (TROWS + 2) * 112; idx += 128) {
    int r = idx / 112, s = idx - r * 112;
    int gr = rb - 1 + r;
    float v = (gr >= 0 && gr < HH) ? xp[gr * WW + s] : 0.f;
    ts[r * 114 + s + 1] = v;
  }
  for (int r = tid; r < TROWS + 2; r += 128) { ts[r*114] = 0.f; ts[r*114 + 113] = 0.f; }

  float w[9];
  const float* wp = g_dynw + (size_t)plane * 9;
  #pragma unroll
  for (int k = 0; k < 9; k++) w[k] = wp[k];
  __syncthreads();

  if (tid < WW) {
    const int s = tid;
    float a00 = ts[s],       a01 = ts[s + 1],       a02 = ts[s + 2];
    float a10 = ts[114 + s], a11 = ts[114 + s + 1], a12 = ts[114 + s + 2];
    float* op = out + (size_t)plane * HWPIX + (size_t)rb * WW + s;
    #pragma unroll 4
    for (int r = 0; r < TROWS; r++) {
      float a20 = ts[(r + 2)*114 + s];
      float a21 = ts[(r + 2)*114 + s + 1];
      float a22 = ts[(r + 2)*114 + s + 2];
      float acc = w[0]*a00 + w[1]*a01 + w[2]*a02
                + w[3]*a10 + w[4]*a11 + w[5]*a12
                + w[6]*a20 + w[7]*a21 + w[8]*a22;
      op[(size_t)r * WW] = acc;
      a00 = a10; a01 = a11; a02 = a12;
      a10 = a20; a11 = a21; a12 = a22;
    }
  }
}

extern "C" void kernel_launch(void* const* d_in, const int* in_sizes, int n_in,
                              void* d_out, int out_size)
{
  const float* x    = (const float*)d_in[0];
  const float* Wv   = (const float*)d_in[1];
  const float* bv   = (const float*)d_in[2];
  const float* Wm   = (const float*)d_in[3];
  const float* bm   = (const float*)d_in[4];
  const float* gma  = (const float*)d_in[5];
  const float* bta  = (const float*)d_in[6];
  const float* mu   = (const float*)d_in[7];
  const float* var  = (const float*)d_in[8];
  const float* Wfc  = (const float*)d_in[9];
  const float* bfc  = (const float*)d_in[10];
  float* out = (float*)d_out;

  cudaFuncSetAttribute(attn_ctx_kernel,
                       cudaFuncAttributeMaxDynamicSharedMemorySize, SMEM_BYTES);

  zero_ctx_kernel<<<256, 256>>>();
  attn_ctx_kernel<<<dim3(BLKX, BATCH), 256, SMEM_BYTES>>>(
      x, Wv, bv, Wm, bm, gma, bta, mu, var);
  dynw_kernel<<<1024, 128>>>(Wfc, bfc);
  dwconv_kernel<<<dim3(BATCH * CH, HH / TROWS), 128>>>(x, out);
}

// round 5
// speedup vs baseline: 1.9324x; 1.9324x over previous
#include <cuda_runtime.h>
#include <cuda_bf16.h>
#include <cstdint>

#define BATCH 64
#define CH 64
#define HH 112
#define WW 112
#define HWPIX (HH*WW)          // 12544
#define NP 128                 // pixels per tile
#define TPB 7
#define BLKX 14                // 14*7*128 = 12544
#define EPSV 1e-5f

// device scratch (no cudaMalloc allowed)
__device__ float g_context[BATCH*CH*CH];   // [b][c][d]
__device__ float g_dynw[BATCH*CH*9];       // [b*c][9]

// ---------------- smem layout (bytes) ----------------
// X  : [64 ch][136 stride] bf16  (hi, lo)        -> 2 x 17408
// W  : [128 out][72 stride] bf16 (hi, lo)        -> 2 x 18432
// KV : [128 px][136 stride] bf16 (hi, lo)        -> 2 x 34816
//      cols 0-63 = V (value+bias), cols 64-127 = K (softmaxed)
#define XSTR  136
#define WSTR  72
#define KVSTR 136
#define OFF_XHI 0
#define OFF_XLO 17408
#define OFF_WHI 34816
#define OFF_WLO 53248
#define OFF_KHI 71680
#define OFF_KLO 106496
#define SMEMB   141312

// ---------------- helpers ----------------
__device__ __forceinline__ uint32_t smem_u32(const void* p){
  uint32_t a;
  asm("{ .reg .u64 t; cvta.to.shared.u64 t, %1; cvt.u32.u64 %0, t; }" : "=r"(a) : "l"(p));
  return a;
}
__device__ __forceinline__ void ldsm4(uint32_t* r, uint32_t addr){
  asm volatile("ldmatrix.sync.aligned.m8n8.x4.shared.b16 {%0,%1,%2,%3}, [%4];"
    : "=r"(r[0]), "=r"(r[1]), "=r"(r[2]), "=r"(r[3]) : "r"(addr));
}
__device__ __forceinline__ void ldsm4t(uint32_t* r, uint32_t addr){
  asm volatile("ldmatrix.sync.aligned.m8n8.x4.trans.shared.b16 {%0,%1,%2,%3}, [%4];"
    : "=r"(r[0]), "=r"(r[1]), "=r"(r[2]), "=r"(r[3]) : "r"(addr));
}
__device__ __forceinline__ void mma16816(float* d, const uint32_t* a, uint32_t b0, uint32_t b1){
  asm volatile("mma.sync.aligned.m16n8k16.row.col.f32.bf16.bf16.f32 "
    "{%0,%1,%2,%3}, {%4,%5,%6,%7}, {%8,%9}, {%0,%1,%2,%3};"
    : "+f"(d[0]), "+f"(d[1]), "+f"(d[2]), "+f"(d[3])
    : "r"(a[0]), "r"(a[1]), "r"(a[2]), "r"(a[3]), "r"(b0), "r"(b1));
}
__device__ __forceinline__ float bfhi(float x){
  return __bfloat162float(__float2bfloat16_rn(x));
}
__device__ __forceinline__ uint32_t packbf2(float lo_elem, float hi_elem){
  __nv_bfloat162 t = __floats2bfloat162_rn(lo_elem, hi_elem);  // .x = lo addr elem
  return *(uint32_t*)&t;
}

__global__ void __launch_bounds__(256) zero_ctx_kernel(){
  int i = blockIdx.x * blockDim.x + threadIdx.x;   // 65536 float4
  ((float4*)g_context)[i] = make_float4(0.f,0.f,0.f,0.f);
}

// ============ fused attention: bf16x3 split HMMA ============
__global__ void __launch_bounds__(256, 1) attn_ctx_mma(
    const float* __restrict__ x,
    const float* __restrict__ Wv, const float* __restrict__ bvp,
    const float* __restrict__ Wm, const float* __restrict__ bm,
    const float* __restrict__ gma, const float* __restrict__ bta,
    const float* __restrict__ mu,  const float* __restrict__ var)
{
  extern __shared__ char smc[];
  const uint32_t sb = smem_u32(smc);
  const int tid = threadIdx.x;
  const int w   = tid >> 5;        // warp 0..7
  const int l   = tid & 31;
  const int b   = blockIdx.y;

  const int lk = (l & 7) + 8 * (l >> 4);     // ldmatrix row term
  const int lc = 8 * ((l >> 3) & 1);         // ldmatrix col term
  const int cl2 = 2 * (l & 3);

  // ---- load W (rows 0-63 = Wv, 64-127 = Wm*bnscale), bf16 hi/lo, once ----
  #pragma unroll
  for (int i = 0; i < 8; i++) {
    int f4 = tid + 256 * i;        // 2048 float4
    int o  = f4 >> 4;
    int c4 = (f4 & 15) * 4;
    float4 v;
    float s = 1.f;
    if (o < 64) v = __ldg((const float4*)(Wv + o*64 + c4));
    else {
      int oo = o - 64;
      v = __ldg((const float4*)(Wm + oo*64 + c4));
      s = __ldg(gma + oo) * rsqrtf(__ldg(var + oo) + EPSV);
    }
    v.x *= s; v.y *= s; v.z *= s; v.w *= s;
    float h0 = bfhi(v.x), h1 = bfhi(v.y), h2 = bfhi(v.z), h3 = bfhi(v.w);
    uint32_t* ph = (uint32_t*)(smc + OFF_WHI);
    uint32_t* pl = (uint32_t*)(smc + OFF_WLO);
    int bi = o * (WSTR/2) + (c4 >> 1);
    ph[bi]     = packbf2(v.x, v.y);
    ph[bi + 1] = packbf2(v.z, v.w);
    pl[bi]     = packbf2(v.x - h0, v.y - h1);
    pl[bi + 1] = packbf2(v.z - h2, v.w - h3);
  }

  // ---- per-thread constants: BN shift for K cols, bias for V cols ----
  float kshr[16], bvr[16];
  #pragma unroll
  for (int nt = 0; nt < 8; nt++)
    #pragma unroll
    for (int j = 0; j < 2; j++) {
      int col = nt*8 + cl2 + j;
      bvr[2*nt + j] = __ldg(bvp + col);
      float sc = __ldg(gma + col) * rsqrtf(__ldg(var + col) + EPSV);
      kshr[2*nt + j] = (__ldg(bm + col) - __ldg(mu + col)) * sc + __ldg(bta + col);
    }

  __syncthreads();

  // ---- stage-2 persistent accumulators: warp w -> c[(w>>1)*16 .. +16), d[(w&1)*32 .. +32) ----
  const int c_base = (w >> 1) * 16;
  const int d_base = (w & 1) * 32;
  float acc2[4][4];
  #pragma unroll
  for (int i = 0; i < 4; i++)
    #pragma unroll
    for (int j = 0; j < 4; j++) acc2[i][j] = 0.f;

  // ldmatrix base byte offsets
  const uint32_t a1off = sb + OFF_XHI + (uint32_t)(lk*XSTR + 16*w + lc) * 2;    // +ks*16*XSTR*2 ; lo at +17408
  const uint32_t b1off = sb + OFF_WHI + (uint32_t)(lk*WSTR + lc) * 2;           // +((nb*16)*WSTR + ks*16)*2
  const uint32_t a2off = sb + OFF_KHI + (uint32_t)(lk*KVSTR + 64 + c_base + lc) * 2;
  const uint32_t b2off = sb + OFF_KHI + (uint32_t)(lk*KVSTR + d_base + lc) * 2;

  for (int t = 0; t < TPB; t++) {
    const int n0 = (blockIdx.x * TPB + t) * NP;

    // ---- load X tile [64ch][128px] -> bf16 hi/lo smem, coalesced ----
    const float* xb = x + (size_t)b * CH * HWPIX + n0;
    #pragma unroll
    for (int i = 0; i < 8; i++) {
      int f4  = tid + 256 * i;          // 2048 float4
      int chn = f4 >> 5;
      int pxf = f4 & 31;
      float4 v = __ldg((const float4*)(xb + (size_t)chn * HWPIX) + pxf);
      float h0 = bfhi(v.x), h1 = bfhi(v.y), h2 = bfhi(v.z), h3 = bfhi(v.w);
      uint32_t* ph = (uint32_t*)(smc + OFF_XHI);
      uint32_t* pl = (uint32_t*)(smc + OFF_XLO);
      int bi = chn * (XSTR/2) + (pxf * 4 >> 1);
      ph[bi]     = packbf2(v.x, v.y);
      ph[bi + 1] = packbf2(v.z, v.w);
      pl[bi]     = packbf2(v.x - h0, v.y - h1);
      pl[bi + 1] = packbf2(v.z - h2, v.w - h3);
    }
    __syncthreads();

    // ---- stage 1: D1[16 px rows of warp][128 out] = X @ Wcat^T, bf16x3 ----
    float acc1[16][4];
    #pragma unroll
    for (int i = 0; i < 16; i++)
      #pragma unroll
      for (int j = 0; j < 4; j++) acc1[i][j] = 0.f;

    #pragma unroll
    for (int ks = 0; ks < 4; ks++) {
      uint32_t ah[4], al[4];
      uint32_t astep = (uint32_t)(ks * 16 * XSTR) * 2;
      ldsm4t(ah, a1off + astep);
      ldsm4t(al, a1off + astep + 17408u);
      #pragma unroll
      for (int nb = 0; nb < 8; nb++) {
        uint32_t bh[4], bl[4];
        uint32_t bo = (uint32_t)((nb*16) * WSTR + ks*16) * 2;
        ldsm4(bh, b1off + bo);
        ldsm4(bl, b1off + bo + 18432u);
        mma16816(acc1[2*nb],   ah, bh[0], bh[1]);
        mma16816(acc1[2*nb],   ah, bl[0], bl[1]);
        mma16816(acc1[2*nb],   al, bh[0], bh[1]);
        mma16816(acc1[2*nb+1], ah, bh[2], bh[3]);
        mma16816(acc1[2*nb+1], ah, bl[2], bl[3]);
        mma16816(acc1[2*nb+1], al, bh[2], bh[3]);
      }
    }

    // ---- softmax over channels (K = ntiles 8..15), quad-local ----
    float m0 = -1e30f, m1 = -1e30f;
    #pragma unroll
    for (int nt = 8; nt < 16; nt++)
      #pragma unroll
      for (int j = 0; j < 2; j++) {
        float sh = kshr[(nt-8)*2 + j];
        acc1[nt][j]   += sh;
        acc1[nt][2+j] += sh;
        m0 = fmaxf(m0, acc1[nt][j]);
        m1 = fmaxf(m1, acc1[nt][2+j]);
      }
    m0 = fmaxf(m0, __shfl_xor_sync(0xffffffffu, m0, 1));
    m0 = fmaxf(m0, __shfl_xor_sync(0xffffffffu, m0, 2));
    m1 = fmaxf(m1, __shfl_xor_sync(0xffffffffu, m1, 1));
    m1 = fmaxf(m1, __shfl_xor_sync(0xffffffffu, m1, 2));
    float s0 = 0.f, s1 = 0.f;
    #pragma unroll
    for (int nt = 8; nt < 16; nt++)
      #pragma unroll
      for (int j = 0; j < 2; j++) {
        acc1[nt][j]   = __expf(acc1[nt][j]   - m0); s0 += acc1[nt][j];
        acc1[nt][2+j] = __expf(acc1[nt][2+j] - m1); s1 += acc1[nt][2+j];
      }
    s0 += __shfl_xor_sync(0xffffffffu, s0, 1);
    s0 += __shfl_xor_sync(0xffffffffu, s0, 2);
    s1 += __shfl_xor_sync(0xffffffffu, s1, 1);
    s1 += __shfl_xor_sync(0xffffffffu, s1, 2);
    const float inv0 = 1.f / s0, inv1 = 1.f / s1;

    // ---- write KV smem [px][out] bf16 hi/lo (V cols 0-63 biased, K cols 64-127 normalized) ----
    {
      const int r0 = 16*w + (l >> 2);
      uint32_t* ph = (uint32_t*)(smc + OFF_KHI);
      uint32_t* pl = (uint32_t*)(smc + OFF_KLO);
      #pragma unroll
      for (int nt = 0; nt < 16; nt++) {
        float f0, f1, f2, f3;
        if (nt < 8) {
          f0 = acc1[nt][0] + bvr[2*nt];     f1 = acc1[nt][1] + bvr[2*nt+1];
          f2 = acc1[nt][2] + bvr[2*nt];     f3 = acc1[nt][3] + bvr[2*nt+1];
        } else {
          f0 = acc1[nt][0] * inv0;          f1 = acc1[nt][1] * inv0;
          f2 = acc1[nt][2] * inv1;          f3 = acc1[nt][3] * inv1;
        }
        int col = nt*8 + cl2;
        int bi0 = r0       * (KVSTR/2) + (col >> 1);
        int bi1 = (r0 + 8) * (KVSTR/2) + (col >> 1);
        float h0 = bfhi(f0), h1 = bfhi(f1), h2 = bfhi(f2), h3 = bfhi(f3);
        ph[bi0] = packbf2(f0, f1);          pl[bi0] = packbf2(f0 - h0, f1 - h1);
        ph[bi1] = packbf2(f2, f3);          pl[bi1] = packbf2(f2 - h2, f3 - h3);
      }
    }
    __syncthreads();

    // ---- stage 2: ctx[c,d] += K[c,px] @ V[d,px]^T over 128 px, bf16x3 ----
    #pragma unroll
    for (int ks = 0; ks < 8; ks++) {
      uint32_t step = (uint32_t)(ks * 16 * KVSTR) * 2;
      uint32_t ah[4], al[4];
      ldsm4t(ah, a2off + step);
      ldsm4t(al, a2off + step + 34816u);
      #pragma unroll
      for (int dbi = 0; dbi < 2; dbi++) {
        uint32_t bh[4], bl[4];
        uint32_t bo = step + (uint32_t)(dbi * 16) * 2;
        ldsm4t(bh, b2off + bo);
        ldsm4t(bl, b2off + bo + 34816u);
        // trans-x4 order: r0=b0(nt0), r1=b0(nt1), r2=b1(nt0), r3=b1(nt1)
        mma16816(acc2[2*dbi],   ah, bh[0], bh[2]);
        mma16816(acc2[2*dbi],   ah, bl[0], bl[2]);
        mma16816(acc2[2*dbi],   al, bh[0], bh[2]);
        mma16816(acc2[2*dbi+1], ah, bh[1], bh[3]);
        mma16816(acc2[2*dbi+1], ah, bl[1], bl[3]);
        mma16816(acc2[2*dbi+1], al, bh[1], bh[3]);
      }
    }
    __syncthreads();   // KV + X free for next tile
  }

  // ---- flush context ----
  float* cp = g_context + (size_t)b * CH * CH;
  const int c0 = c_base + (l >> 2);
  #pragma unroll
  for (int nt = 0; nt < 4; nt++)
    #pragma unroll
    for (int j = 0; j < 2; j++) {
      int d = d_base + nt*8 + cl2 + j;
      atomicAdd(cp + c0*CH + d,       acc2[nt][j]);
      atomicAdd(cp + (c0+8)*CH + d,   acc2[nt][2+j]);
    }
}

// dynw[b,i,j] = sum_m sigmoid(context[b,i,m]) * Wfc[i,j,m] + bfc[i,j]
__global__ void __launch_bounds__(128) dynw_kernel(
    const float* __restrict__ Wfc, const float* __restrict__ bfc)
{
  int warp = blockIdx.x * 4 + (threadIdx.x >> 5);   // 0..4095
  int lane = threadIdx.x & 31;
  int i = warp & 63;
  const float* ctx = g_context + (size_t)warp * 64;
  float a0 = 1.f / (1.f + __expf(-ctx[lane]));
  float a1 = 1.f / (1.f + __expf(-ctx[lane + 32]));
  #pragma unroll
  for (int j = 0; j < 9; j++) {
    float s = a0 * Wfc[(i*9 + j)*64 + lane] + a1 * Wfc[(i*9 + j)*64 + lane + 32];
    #pragma unroll
    for (int o = 16; o > 0; o >>= 1) s += __shfl_xor_sync(0xffffffffu, s, o);
    if (lane == 0) g_dynw[warp*9 + j] = s + bfc[i*9 + j];
  }
}

// depthwise 3x3, pad 1, per-(b,c) weights from g_dynw
#define TROWS 28
__global__ void __launch_bounds__(128) dwconv_kernel(
    const float* __restrict__ x, float* __restrict__ out)
{
  __shared__ float ts[(TROWS + 2) * 114];
  const int plane = blockIdx.x;                 // b*64 + c
  const int rb = blockIdx.y * TROWS;
  const float* xp = x + (size_t)plane * HWPIX;
  const int tid = threadIdx.x;

  for (int idx = tid; idx < (TROWS + 2) * 112; idx += 128) {
    int r = idx / 112, s = idx - r * 112;
    int gr = rb - 1 + r;
    float v = (gr >= 0 && gr < HH) ? xp[gr * WW + s] : 0.f;
    ts[r * 114 + s + 1] = v;
  }
  for (int r = tid; r < TROWS + 2; r += 128) { ts[r*114] = 0.f; ts[r*114 + 113] = 0.f; }

  float w[9];
  const float* wp = g_dynw + (size_t)plane * 9;
  #pragma unroll
  for (int k = 0; k < 9; k++) w[k] = wp[k];
  __syncthreads();

  if (tid < WW) {
    const int s = tid;
    float a00 = ts[s],       a01 = ts[s + 1],       a02 = ts[s + 2];
    float a10 = ts[114 + s], a11 = ts[114 + s + 1], a12 = ts[114 + s + 2];
    float* op = out + (size_t)plane * HWPIX + (size_t)rb * WW + s;
    #pragma unroll 4
    for (int r = 0; r < TROWS; r++) {
      float a20 = ts[(r + 2)*114 + s];
      float a21 = ts[(r + 2)*114 + s + 1];
      float a22 = ts[(r + 2)*114 + s + 2];
      float acc = w[0]*a00 + w[1]*a01 + w[2]*a02
                + w[3]*a10 + w[4]*a11 + w[5]*a12
                + w[6]*a20 + w[7]*a21 + w[8]*a22;
      op[(size_t)r * WW] = acc;
      a00 = a10; a01 = a11; a02 = a12;
      a10 = a20; a11 = a21; a12 = a22;
    }
  }
}

extern "C" void kernel_launch(void* const* d_in, const int* in_sizes, int n_in,
                              void* d_out, int out_size)
{
  const float* x    = (const float*)d_in[0];
  const float* Wv   = (const float*)d_in[1];
  const float* bv   = (const float*)d_in[2];
  const float* Wm   = (const float*)d_in[3];
  const float* bm   = (const float*)d_in[4];
  const float* gma  = (const float*)d_in[5];
  const float* bta  = (const float*)d_in[6];
  const float* mu   = (const float*)d_in[7];
  const float* var  = (const float*)d_in[8];
  const float* Wfc  = (const float*)d_in[9];
  const float* bfc  = (const float*)d_in[10];
  float* out = (float*)d_out;

  cudaFuncSetAttribute(attn_ctx_mma,
                       cudaFuncAttributeMaxDynamicSharedMemorySize, SMEMB);

  zero_ctx_kernel<<<256, 256>>>();
  attn_ctx_mma<<<dim3(BLKX, BATCH), 256, SMEMB>>>(
      x, Wv, bv, Wm, bm, gma, bta, mu, var);
  dynw_kernel<<<1024, 128>>>(Wfc, bfc);
  dwconv_kernel<<<dim3(BATCH * CH, HH / TROWS), 128>>>(x, out);
}

// round 6
// speedup vs baseline: 2.3813x; 1.2323x over previous
#include <cuda_runtime.h>
#include <cuda_bf16.h>
#include <cstdint>

#define BATCH 64
#define CH 64
#define HH 112
#define WW 112
#define HWPIX (HH*WW)          // 12544
#define NP 128                 // pixels per tile
#define TPB 7
#define BLKX 14                // 14*7*128 = 12544
#define EPSV 1e-5f

// device scratch (no cudaMalloc allowed)
__device__ float g_context[BATCH*CH*CH];   // [b][c][d]
__device__ float g_dynw[BATCH*CH*9];       // [b*c][9]

// ---------------- smem layout (bytes) ----------------
// X  : [64 ch][136 stride] bf16 (hi,lo), DOUBLE buffered
// W  : [128 out][72 stride] bf16 (hi,lo)
// KV : [128 px][136 stride] bf16 (hi,lo); cols 0-63 = V, 64-127 = K
#define XSTR  136
#define WSTR  72
#define KVSTR 136
#define OFF_XHI0 0
#define OFF_XLO0 17408
#define OFF_XHI1 34816
#define OFF_XLO1 52224
#define OFF_WHI  69632
#define OFF_WLO  88064
#define OFF_KHI  106496
#define OFF_KLO  141312
#define SMEMB    176128

// ---------------- helpers ----------------
__device__ __forceinline__ uint32_t smem_u32(const void* p){
  uint32_t a;
  asm("{ .reg .u64 t; cvta.to.shared.u64 t, %1; cvt.u32.u64 %0, t; }" : "=r"(a) : "l"(p));
  return a;
}
__device__ __forceinline__ void ldsm4(uint32_t* r, uint32_t addr){
  asm volatile("ldmatrix.sync.aligned.m8n8.x4.shared.b16 {%0,%1,%2,%3}, [%4];"
    : "=r"(r[0]), "=r"(r[1]), "=r"(r[2]), "=r"(r[3]) : "r"(addr));
}
__device__ __forceinline__ void ldsm4t(uint32_t* r, uint32_t addr){
  asm volatile("ldmatrix.sync.aligned.m8n8.x4.trans.shared.b16 {%0,%1,%2,%3}, [%4];"
    : "=r"(r[0]), "=r"(r[1]), "=r"(r[2]), "=r"(r[3]) : "r"(addr));
}
__device__ __forceinline__ void mma16816(float* d, const uint32_t* a, uint32_t b0, uint32_t b1){
  asm volatile("mma.sync.aligned.m16n8k16.row.col.f32.bf16.bf16.f32 "
    "{%0,%1,%2,%3}, {%4,%5,%6,%7}, {%8,%9}, {%0,%1,%2,%3};"
    : "+f"(d[0]), "+f"(d[1]), "+f"(d[2]), "+f"(d[3])
    : "r"(a[0]), "r"(a[1]), "r"(a[2]), "r"(a[3]), "r"(b0), "r"(b1));
}
// truncation split: hi = bits & 0xffff0000 (exact bf16), lo = rn_bf16(f - hi)
__device__ __forceinline__ void split_store(uint32_t* ph, uint32_t* pl, int bi,
                                            float f0, float f1){
  uint32_t u0 = __float_as_uint(f0), u1 = __float_as_uint(f1);
  ph[bi] = __byte_perm(u0, u1, 0x7632);                 // [hi16(u0), hi16(u1)]
  float h0 = __uint_as_float(u0 & 0xffff0000u);
  float h1 = __uint_as_float(u1 & 0xffff0000u);
  __nv_bfloat162 t = __floats2bfloat162_rn(f0 - h0, f1 - h1);
  pl[bi] = *(uint32_t*)&t;
}

__global__ void __launch_bounds__(256) zero_ctx_kernel(){
  int i = blockIdx.x * blockDim.x + threadIdx.x;   // 65536 float4
  ((float4*)g_context)[i] = make_float4(0.f,0.f,0.f,0.f);
}

// ============ fused attention: bf16x3 split HMMA, pipelined ============
__global__ void __launch_bounds__(256, 1) attn_ctx_mma(
    const float* __restrict__ x,
    const float* __restrict__ Wv, const float* __restrict__ bvp,
    const float* __restrict__ Wm, const float* __restrict__ bm,
    const float* __restrict__ gma, const float* __restrict__ bta,
    const float* __restrict__ mu,  const float* __restrict__ var)
{
  extern __shared__ char smc[];
  const uint32_t sb = smem_u32(smc);
  const int tid = threadIdx.x;
  const int w   = tid >> 5;        // warp 0..7
  const int l   = tid & 31;
  const int b   = blockIdx.y;

  const int lk = (l & 7) + 8 * (l >> 4);     // ldmatrix row term
  const int lc = 8 * ((l >> 3) & 1);         // ldmatrix col term
  const int cl2 = 2 * (l & 3);

  const float* xb = x + (size_t)b * CH * HWPIX;

  // ---- prefetch X tile 0 into registers (hide DRAM behind W fill) ----
  float4 xr[8];
  {
    const int n0 = blockIdx.x * TPB * NP;
    #pragma unroll
    for (int i = 0; i < 8; i++) {
      int f4 = tid + 256 * i;
      int chn = f4 >> 5, pxf = f4 & 31;
      xr[i] = __ldg((const float4*)(xb + (size_t)chn * HWPIX + n0) + pxf);
    }
  }

  // ---- load W (rows 0-63 = Wv, 64-127 = Wm*bnscale), bf16 hi/lo, once ----
  {
    uint32_t* ph = (uint32_t*)(smc + OFF_WHI);
    uint32_t* pl = (uint32_t*)(smc + OFF_WLO);
    #pragma unroll
    for (int i = 0; i < 8; i++) {
      int f4 = tid + 256 * i;        // 2048 float4
      int o  = f4 >> 4;
      int c4 = (f4 & 15) * 4;
      float4 v;
      float s = 1.f;
      if (o < 64) v = __ldg((const float4*)(Wv + o*64 + c4));
      else {
        int oo = o - 64;
        v = __ldg((const float4*)(Wm + oo*64 + c4));
        s = __ldg(gma + oo) * rsqrtf(__ldg(var + oo) + EPSV);
      }
      v.x *= s; v.y *= s; v.z *= s; v.w *= s;
      int bi = o * (WSTR/2) + (c4 >> 1);
      split_store(ph, pl, bi,     v.x, v.y);
      split_store(ph, pl, bi + 1, v.z, v.w);
    }
  }

  // ---- per-thread constants: BN shift for K cols, bias for V cols ----
  float kshr[16], bvr[16];
  #pragma unroll
  for (int nt = 0; nt < 8; nt++)
    #pragma unroll
    for (int j = 0; j < 2; j++) {
      int col = nt*8 + cl2 + j;
      bvr[2*nt + j] = __ldg(bvp + col);
      float sc = __ldg(gma + col) * rsqrtf(__ldg(var + col) + EPSV);
      kshr[2*nt + j] = (__ldg(bm + col) - __ldg(mu + col)) * sc + __ldg(bta + col);
    }

  // ---- stage-2 persistent accumulators ----
  const int c_base = (w >> 1) * 16;
  const int d_base = (w & 1) * 32;
  float acc2[4][4];
  #pragma unroll
  for (int i = 0; i < 4; i++)
    #pragma unroll
    for (int j = 0; j < 4; j++) acc2[i][j] = 0.f;

  // ldmatrix base byte offsets
  const uint32_t a1term = (uint32_t)(lk*XSTR + 16*w + lc) * 2;
  const uint32_t b1off  = sb + OFF_WHI + (uint32_t)(lk*WSTR + lc) * 2;
  const uint32_t a2off  = sb + OFF_KHI + (uint32_t)(lk*KVSTR + 64 + c_base + lc) * 2;
  const uint32_t b2off  = sb + OFF_KHI + (uint32_t)(lk*KVSTR + d_base + lc) * 2;

  for (int t = 0; t < TPB; t++) {
    const uint32_t xhi = (t & 1) ? OFF_XHI1 : OFF_XHI0;

    // ---- convert + store X(t) from regs into buffer t&1 ----
    {
      uint32_t* ph = (uint32_t*)(smc + xhi);
      uint32_t* pl = (uint32_t*)(smc + xhi + 17408);
      #pragma unroll
      for (int i = 0; i < 8; i++) {
        int f4  = tid + 256 * i;
        int chn = f4 >> 5, pxf = f4 & 31;
        int bi = chn * (XSTR/2) + pxf * 2;
        split_store(ph, pl, bi,     xr[i].x, xr[i].y);
        split_store(ph, pl, bi + 1, xr[i].z, xr[i].w);
      }
    }
    __syncthreads();

    // ---- prefetch X(t+1) (latency hidden behind stage1 MMAs) ----
    if (t + 1 < TPB) {
      const int n1 = (blockIdx.x * TPB + t + 1) * NP;
      #pragma unroll
      for (int i = 0; i < 8; i++) {
        int f4 = tid + 256 * i;
        int chn = f4 >> 5, pxf = f4 & 31;
        xr[i] = __ldg((const float4*)(xb + (size_t)chn * HWPIX + n1) + pxf);
      }
    }

    // ---- stage 1: D1[16 px rows of warp][128 out] = X @ Wcat^T, bf16x3 ----
    float acc1[16][4];
    #pragma unroll
    for (int i = 0; i < 16; i++)
      #pragma unroll
      for (int j = 0; j < 4; j++) acc1[i][j] = 0.f;

    const uint32_t a1off = sb + xhi + a1term;
    #pragma unroll
    for (int ks = 0; ks < 4; ks++) {
      uint32_t ah[4], al[4];
      uint32_t astep = (uint32_t)(ks * 16 * XSTR) * 2;
      ldsm4t(ah, a1off + astep);
      ldsm4t(al, a1off + astep + 17408u);
      #pragma unroll
      for (int nb = 0; nb < 8; nb++) {
        uint32_t bh[4], bl[4];
        uint32_t bo = (uint32_t)((nb*16) * WSTR + ks*16) * 2;
        ldsm4(bh, b1off + bo);
        ldsm4(bl, b1off + bo + 18432u);
        mma16816(acc1[2*nb],   ah, bh[0], bh[1]);
        mma16816(acc1[2*nb],   ah, bl[0], bl[1]);
        mma16816(acc1[2*nb],   al, bh[0], bh[1]);
        mma16816(acc1[2*nb+1], ah, bh[2], bh[3]);
        mma16816(acc1[2*nb+1], ah, bl[2], bl[3]);
        mma16816(acc1[2*nb+1], al, bh[2], bh[3]);
      }
    }

    // ---- softmax over channels (K = ntiles 8..15), quad-local ----
    float m0 = -1e30f, m1 = -1e30f;
    #pragma unroll
    for (int nt = 8; nt < 16; nt++)
      #pragma unroll
      for (int j = 0; j < 2; j++) {
        float sh = kshr[(nt-8)*2 + j];
        acc1[nt][j]   += sh;
        acc1[nt][2+j] += sh;
        m0 = fmaxf(m0, acc1[nt][j]);
        m1 = fmaxf(m1, acc1[nt][2+j]);
      }
    m0 = fmaxf(m0, __shfl_xor_sync(0xffffffffu, m0, 1));
    m0 = fmaxf(m0, __shfl_xor_sync(0xffffffffu, m0, 2));
    m1 = fmaxf(m1, __shfl_xor_sync(0xffffffffu, m1, 1));
    m1 = fmaxf(m1, __shfl_xor_sync(0xffffffffu, m1, 2));
    float s0 = 0.f, s1 = 0.f;
    #pragma unroll
    for (int nt = 8; nt < 16; nt++)
      #pragma unroll
      for (int j = 0; j < 2; j++) {
        acc1[nt][j]   = __expf(acc1[nt][j]   - m0); s0 += acc1[nt][j];
        acc1[nt][2+j] = __expf(acc1[nt][2+j] - m1); s1 += acc1[nt][2+j];
      }
    s0 += __shfl_xor_sync(0xffffffffu, s0, 1);
    s0 += __shfl_xor_sync(0xffffffffu, s0, 2);
    s1 += __shfl_xor_sync(0xffffffffu, s1, 1);
    s1 += __shfl_xor_sync(0xffffffffu, s1, 2);
    const float inv0 = 1.f / s0, inv1 = 1.f / s1;

    // ---- write KV smem [px][out] bf16 hi/lo ----
    {
      const int r0 = 16*w + (l >> 2);
      uint32_t* ph = (uint32_t*)(smc + OFF_KHI);
      uint32_t* pl = (uint32_t*)(smc + OFF_KLO);
      #pragma unroll
      for (int nt = 0; nt < 16; nt++) {
        float f0, f1, f2, f3;
        if (nt < 8) {
          f0 = acc1[nt][0] + bvr[2*nt];     f1 = acc1[nt][1] + bvr[2*nt+1];
          f2 = acc1[nt][2] + bvr[2*nt];     f3 = acc1[nt][3] + bvr[2*nt+1];
        } else {
          f0 = acc1[nt][0] * inv0;          f1 = acc1[nt][1] * inv0;
          f2 = acc1[nt][2] * inv1;          f3 = acc1[nt][3] * inv1;
        }
        int col = nt*8 + cl2;
        int bi0 = r0       * (KVSTR/2) + (col >> 1);
        int bi1 = (r0 + 8) * (KVSTR/2) + (col >> 1);
        split_store(ph, pl, bi0, f0, f1);
        split_store(ph, pl, bi1, f2, f3);
      }
    }
    __syncthreads();

    // ---- stage 2: ctx[c,d] += K[c,px] @ V[d,px]^T over 128 px, bf16x3 ----
    #pragma unroll
    for (int ks = 0; ks < 8; ks++) {
      uint32_t step = (uint32_t)(ks * 16 * KVSTR) * 2;
      uint32_t ah[4], al[4];
      ldsm4t(ah, a2off + step);
      ldsm4t(al, a2off + step + 34816u);
      #pragma unroll
      for (int dbi = 0; dbi < 2; dbi++) {
        uint32_t bh[4], bl[4];
        uint32_t bo = step + (uint32_t)(dbi * 16) * 2;
        ldsm4t(bh, b2off + bo);
        ldsm4t(bl, b2off + bo + 34816u);
        mma16816(acc2[2*dbi],   ah, bh[0], bh[2]);
        mma16816(acc2[2*dbi],   ah, bl[0], bl[2]);
        mma16816(acc2[2*dbi],   al, bh[0], bh[2]);
        mma16816(acc2[2*dbi+1], ah, bh[1], bh[3]);
        mma16816(acc2[2*dbi+1], ah, bl[1], bl[3]);
        mma16816(acc2[2*dbi+1], al, bh[1], bh[3]);
      }
    }
    // no trailing barrier: X is double-buffered; KV(t) last read here, next
    // write to KV happens after sync1 of iter t+1 → all warps past stage2(t).
  }

  // ---- flush context ----
  float* cp = g_context + (size_t)b * CH * CH;
  const int c0 = c_base + (l >> 2);
  #pragma unroll
  for (int nt = 0; nt < 4; nt++)
    #pragma unroll
    for (int j = 0; j < 2; j++) {
      int d = d_base + nt*8 + cl2 + j;
      atomicAdd(cp + c0*CH + d,       acc2[nt][j]);
      atomicAdd(cp + (c0+8)*CH + d,   acc2[nt][2+j]);
    }
}

// dynw[b,i,j] = sum_m sigmoid(context[b,i,m]) * Wfc[i,j,m] + bfc[i,j]
__global__ void __launch_bounds__(128) dynw_kernel(
    const float* __restrict__ Wfc, const float* __restrict__ bfc)
{
  int warp = blockIdx.x * 4 + (threadIdx.x >> 5);   // 0..4095
  int lane = threadIdx.x & 31;
  int i = warp & 63;
  const float* ctx = g_context + (size_t)warp * 64;
  float a0 = 1.f / (1.f + __expf(-ctx[lane]));
  float a1 = 1.f / (1.f + __expf(-ctx[lane + 32]));
  #pragma unroll
  for (int j = 0; j < 9; j++) {
    float s = a0 * Wfc[(i*9 + j)*64 + lane] + a1 * Wfc[(i*9 + j)*64 + lane + 32];
    #pragma unroll
    for (int o = 16; o > 0; o >>= 1) s += __shfl_xor_sync(0xffffffffu, s, o);
    if (lane == 0) g_dynw[warp*9 + j] = s + bfc[i*9 + j];
  }
}

// depthwise 3x3, pad 1 — float4 per thread, 4 row-groups of 7 rows
#define TROWS 28
#define TS_STR 120
__global__ void __launch_bounds__(128) dwconv_kernel(
    const float* __restrict__ x, float* __restrict__ out)
{
  __shared__ float ts[(TROWS + 2) * TS_STR];   // data col s at idx s+4
  const int plane = blockIdx.x;                 // b*64 + c
  const int rb = blockIdx.y * TROWS;
  const float* xp = x + (size_t)plane * HWPIX;
  const int tid = threadIdx.x;

  // float4 fill: 30 rows x 28 float4
  for (int i = tid; i < 840; i += 128) {
    int r = i / 28, k = i - r * 28;
    int gr = rb - 1 + r;
    float4 v = make_float4(0.f, 0.f, 0.f, 0.f);
    if (gr >= 0 && gr < HH) v = __ldg((const float4*)(xp + (size_t)gr * WW) + k);
    *(float4*)&ts[r * TS_STR + 4 + 4*k] = v;
  }
  for (int i = tid; i < 30; i += 128) { ts[i*TS_STR + 3] = 0.f; ts[i*TS_STR + 116] = 0.f; }

  float w[9];
  const float* wp = g_dynw + (size_t)plane * 9;
  #pragma unroll
  for (int k = 0; k < 9; k++) w[k] = __ldg(wp + k);
  __syncthreads();

  if (tid < 112) {
    const int g  = tid / 28;         // row group 0..3 (7 rows each)
    const int c4 = tid - g * 28;     // float4 column 0..27
    const float* rp = ts + (g*7) * TS_STR + 4*c4 + 3;
    float  L0 = rp[0];  float4 F0 = *(const float4*)(rp + 1);  float R0 = rp[5];
    rp += TS_STR;
    float  L1 = rp[0];  float4 F1 = *(const float4*)(rp + 1);  float R1 = rp[5];
    float* op = out + (size_t)plane * HWPIX + (size_t)(rb + g*7) * WW + 4*c4;
    #pragma unroll
    for (int j = 0; j < 7; j++) {
      rp += TS_STR;
      float  L2 = rp[0];  float4 F2 = *(const float4*)(rp + 1);  float R2 = rp[5];
      float4 o;
      o.x = w[0]*L0   + w[1]*F0.x + w[2]*F0.y
          + w[3]*L1   + w[4]*F1.x + w[5]*F1.y
          + w[6]*L2   + w[7]*F2.x + w[8]*F2.y;
      o.y = w[0]*F0.x + w[1]*F0.y + w[2]*F0.z
          + w[3]*F1.x + w[4]*F1.y + w[5]*F1.z
          + w[6]*F2.x + w[7]*F2.y + w[8]*F2.z;
      o.z = w[0]*F0.y + w[1]*F0.z + w[2]*F0.w
          + w[3]*F1.y + w[4]*F1.z + w[5]*F1.w
          + w[6]*F2.y + w[7]*F2.z + w[8]*F2.w;
      o.w = w[0]*F0.z + w[1]*F0.w + w[2]*R0
          + w[3]*F1.z + w[4]*F1.w + w[5]*R1
          + w[6]*F2.z + w[7]*F2.w + w[8]*R2;
      *(float4*)op = o;
      op += WW;
      L0 = L1; F0 = F1; R0 = R1;
      L1 = L2; F1 = F2; R1 = R2;
    }
  }
}

extern "C" void kernel_launch(void* const* d_in, const int* in_sizes, int n_in,
                              void* d_out, int out_size)
{
  const float* x    = (const float*)d_in[0];
  const float* Wv   = (const float*)d_in[1];
  const float* bv   = (const float*)d_in[2];
  const float* Wm   = (const float*)d_in[3];
  const float* bm   = (const float*)d_in[4];
  const float* gma  = (const float*)d_in[5];
  const float* bta  = (const float*)d_in[6];
  const float* mu   = (const float*)d_in[7];
  const float* var  = (const float*)d_in[8];
  const float* Wfc  = (const float*)d_in[9];
  const float* bfc  = (const float*)d_in[10];
  float* out = (float*)d_out;

  cudaFuncSetAttribute(attn_ctx_mma,
                       cudaFuncAttributeMaxDynamicSharedMemorySize, SMEMB);

  zero_ctx_kernel<<<256, 256>>>();
  attn_ctx_mma<<<dim3(BLKX, BATCH), 256, SMEMB>>>(
      x, Wv, bv, Wm, bm, gma, bta, mu, var);
  dynw_kernel<<<1024, 128>>>(Wfc, bfc);
  dwconv_kernel<<<dim3(BATCH * CH, HH / TROWS), 128>>>(x, out);
}